// round 3
// baseline (speedup 1.0000x reference)
#include <cuda_runtime.h>
#include <cstdint>

// Problem constants
constexpr int BB = 32;       // batch
constexpr int TT = 2048;     // time steps

// ---------------- scratch (static device globals; no allocation allowed) ----
__device__ float g_xg[(size_t)BB * TT * 3072];     // input-gate projections, max 3H=3072
__device__ float g_act0[(size_t)BB * TT * 1024];   // activation ping
__device__ float g_act1[(size_t)BB * TT * 1024];   // activation pong
__device__ float g_h[2 * 32 * 1024];               // hidden state, double buffered, layout f4[k>>2][b][k&3]
__device__ unsigned g_cnt;                          // grid barrier counter
__device__ unsigned g_gen;                          // grid barrier generation

// ---------------- packed f32x2 helpers (sm_100+) ---------------------------
__device__ __forceinline__ void fma2(unsigned long long& a, unsigned long long x, unsigned long long y) {
    asm("fma.rn.f32x2 %0, %1, %2, %0;" : "+l"(a) : "l"(x), "l"(y));
}
__device__ __forceinline__ unsigned long long pk2(float x, float y) {
    unsigned long long r; asm("mov.b64 %0, {%1,%2};" : "=l"(r) : "f"(x), "f"(y)); return r;
}
__device__ __forceinline__ float2 up2(unsigned long long v) {
    float2 f; asm("mov.b64 {%0,%1}, %2;" : "=f"(f.x), "=f"(f.y) : "l"(v)); return f;
}

union HU { float4 f; ulonglong2 u; };
__device__ __forceinline__ HU ldcg4(const float4* p) { HU r; r.f = __ldcg(p); return r; }

// ---------------- input projection GEMM -------------------------------------
// C[m, n] = sum_k A[m, k] * W[n, k] + bias[n],  m = b*TT + t
// A element address = A + b*sb + t*st + k*sk   (handles both [B,C,T] and [B,T,C])
// Tile: BM=128, BN=64, BK=16; 256 threads; per-thread 8x4 via f32x2 row pairs.
// Bs is stored pre-duplicated as packed (b,b) f32x2 pairs to remove MOVs from
// the inner loop.
__global__ __launch_bounds__(256) void gemm_xg(
    const float* __restrict__ A, const float* __restrict__ W,
    const float* __restrict__ bias, float* __restrict__ C,
    int K, int N3, long sb, long st, long sk)
{
    __shared__ __align__(16) float As[16][128];
    __shared__ __align__(16) unsigned long long Bs2[16][64];

    int tid = threadIdx.x;
    int n0 = blockIdx.x * 64;
    int m0 = blockIdx.y * 128;
    int bidx = m0 / TT;
    int t0 = m0 % TT;          // TT % 128 == 0 so tile stays within one batch row
    const float* Ab = A + (size_t)bidx * sb + (size_t)t0 * st;
    int tx = tid & 15, ty = tid >> 4;

    unsigned long long acc2[4][4];
#pragma unroll
    for (int i = 0; i < 4; ++i)
#pragma unroll
        for (int j = 0; j < 4; ++j) acc2[i][j] = 0ull;

    for (int k0 = 0; k0 < K; k0 += 16) {
        if (sk == 1) {
            // k contiguous (layers 1-3): each thread loads a float4 along k
#pragma unroll
            for (int i = 0; i < 2; ++i) {
                int lin = tid + i * 256;
                int m = lin >> 2, k4 = (lin & 3) * 4;
                const float* p = Ab + (size_t)m * st + (k0 + k4);
                float4 v = *(const float4*)p;
                As[k4 + 0][m] = v.x; As[k4 + 1][m] = v.y;
                As[k4 + 2][m] = v.z; As[k4 + 3][m] = v.w;
            }
        } else {
            // t contiguous (layer 0, x is [B,C,T]): float4 along m
#pragma unroll
            for (int i = 0; i < 2; ++i) {
                int lin = tid + i * 256;
                int k = lin >> 5, m4 = (lin & 31) * 4;
                const float* p = Ab + m4 + (size_t)(k0 + k) * sk;
                *(float4*)&As[k][m4] = *(const float4*)p;
            }
        }
        {
            int n = tid >> 2, k4 = (tid & 3) * 4;
            float4 v = *(const float4*)&W[(size_t)(n0 + n) * K + k0 + k4];
            Bs2[k4 + 0][n] = pk2(v.x, v.x);
            Bs2[k4 + 1][n] = pk2(v.y, v.y);
            Bs2[k4 + 2][n] = pk2(v.z, v.z);
            Bs2[k4 + 3][n] = pk2(v.w, v.w);
        }
        __syncthreads();

#pragma unroll
        for (int k = 0; k < 16; ++k) {
            const ulonglong2* ap = (const ulonglong2*)&As[k][ty * 8];
            ulonglong2 A0 = ap[0], A1 = ap[1];
            unsigned long long am[4] = {A0.x, A0.y, A1.x, A1.y};
            const ulonglong2* bp = (const ulonglong2*)&Bs2[k][tx * 4];
            ulonglong2 B01 = bp[0], B23 = bp[1];
            unsigned long long bd[4] = {B01.x, B01.y, B23.x, B23.y};
#pragma unroll
            for (int mp = 0; mp < 4; ++mp)
#pragma unroll
                for (int j = 0; j < 4; ++j) fma2(acc2[mp][j], am[mp], bd[j]);
        }
        __syncthreads();
    }

    float4 bv = *(const float4*)&bias[n0 + tx * 4];
#pragma unroll
    for (int mp = 0; mp < 4; ++mp) {
        float2 c0 = up2(acc2[mp][0]), c1 = up2(acc2[mp][1]);
        float2 c2 = up2(acc2[mp][2]), c3 = up2(acc2[mp][3]);
        size_t r0 = (size_t)(m0 + ty * 8 + 2 * mp) * N3 + n0 + tx * 4;
        float4 o0 = {c0.x + bv.x, c1.x + bv.y, c2.x + bv.z, c3.x + bv.w};
        float4 o1 = {c0.y + bv.x, c1.y + bv.y, c2.y + bv.z, c3.y + bv.w};
        *(float4*)&C[r0] = o0;
        *(float4*)&C[r0 + N3] = o1;
    }
}

// ---------------- zero hidden state ----------------------------------------
__global__ void zero_h_kernel() {
    int i = blockIdx.x * blockDim.x + threadIdx.x;
    if (i < 2 * 32 * 1024) g_h[i] = 0.f;
}

// ---------------- persistent GRU recurrence --------------------------------
// Grid = 128 CTAs; CTA owns HC hidden indices (3*HC rows of w_hh in SMEM).
// Each step: warps load their k-slice of h DIRECTLY from global L2 (ld.cg,
// software-pipelined) — no SMEM staging. 8 warps split K 8-ways, accumulate
// all 3*HC rows with f32x2 FMAs, reduce via SMEM, apply gates (h_prev held in
// a register, xg prefetched at step start), write h_new + output, grid barrier.
template<int K, int HC>
__global__ __launch_bounds__(256) void recur_kernel(
    const float* __restrict__ xg, const float* __restrict__ w_hh,
    const float* __restrict__ b_hh, float* __restrict__ out,
    long os_b, long os_t, long os_j)
{
    constexpr int NR = 3 * HC;
    constexpr int H = K;
    constexpr int k4n = K / 32;              // float4 k-groups per warp
    extern __shared__ float smem[];
    float* w_s = smem;                        // [NR][K]
    float* red = smem + NR * K;               // [8*NR*32]

    int tid = threadIdx.x;
    int cta = blockIdx.x;
    int G = gridDim.x;
    int j0 = cta * HC;

    // load this CTA's w_hh rows into SMEM (rows: gate*H + j0 + jl)
    for (int r = 0; r < NR; ++r) {
        int gate = r / HC, jl = r % HC;
        const float* src = w_hh + (size_t)(gate * H + j0 + jl) * K;
        for (int k = tid * 4; k < K; k += 1024)
            *(float4*)&w_s[r * K + k] = *(const float4*)&src[k];
    }
    unsigned local_gen = 0;
    if (tid == 0) local_gen = *(volatile unsigned*)&g_gen;
    __syncthreads();

    int warp = tid >> 5, lane = tid & 31;
    int k4b = warp * k4n;
    const float* ws2 = w_s + k4b * 4;

    int ejl = tid >> 5, eb = tid & 31;
    bool epi = tid < HC * 32;
    int jg = j0 + ejl;
    int hidx = (jg >> 2) * 128 + eb * 4 + (jg & 3);
    const float* xgbase = xg + (size_t)eb * TT * (3 * H) + jg;
    float bh0 = 0.f, bh1 = 0.f, bh2 = 0.f;
    if (epi) { bh0 = b_hh[jg]; bh1 = b_hh[H + jg]; bh2 = b_hh[2 * H + jg]; }
    float hreg = 0.f;

    for (int t = 0; t < TT; ++t) {
        int p = t & 1;

        // prefetch xg for this step (hidden under the dot-product phase)
        float xr = 0.f, xz = 0.f, xn = 0.f;
        if (epi) {
            const float* xp = xgbase + (size_t)t * (3 * H);
            xr = __ldcs(xp); xz = __ldcs(xp + H); xn = __ldcs(xp + 2 * H);
        }

        const float4* hp = (const float4*)&g_h[p * 32 * 1024];

        unsigned long long acc[NR];
#pragma unroll
        for (int r = 0; r < NR; ++r) acc[r] = 0ull;

        // software-pipelined (depth 2, unroll 2) direct-L2 h loads + FMAs
        HU h0 = ldcg4(hp + (size_t)(k4b + 0) * 32 + lane);
        HU h1 = ldcg4(hp + (size_t)(k4b + 1) * 32 + lane);
        for (int i = 0; i < k4n; i += 2) {
            HU a0 = h0, a1 = h1;
            if (i + 2 < k4n) h0 = ldcg4(hp + (size_t)(k4b + i + 2) * 32 + lane);
            if (i + 3 < k4n) h1 = ldcg4(hp + (size_t)(k4b + i + 3) * 32 + lane);
#pragma unroll
            for (int r = 0; r < NR; ++r) {
                const ulonglong2* wr = (const ulonglong2*)&ws2[r * K + i * 4];
                ulonglong2 w0 = wr[0], w1 = wr[1];
                fma2(acc[r], a0.u.x, w0.x);
                fma2(acc[r], a0.u.y, w0.y);
                fma2(acc[r], a1.u.x, w1.x);
                fma2(acc[r], a1.u.y, w1.y);
            }
        }

        // cross-warp reduction via SMEM
#pragma unroll
        for (int r = 0; r < NR; ++r) {
            float2 f = up2(acc[r]);
            red[(warp * NR + r) * 32 + lane] = f.x + f.y;
        }
        __syncthreads();

        if (epi) {
            float s[3];
#pragma unroll
            for (int gate = 0; gate < 3; ++gate) {
                float v = (gate == 0) ? bh0 : (gate == 1) ? bh1 : bh2;
#pragma unroll
                for (int w = 0; w < 8; ++w)
                    v += red[(w * NR + gate * HC + ejl) * 32 + eb];
                s[gate] = v;
            }
            float r_ = 1.f / (1.f + __expf(-(xr + s[0])));
            float z_ = 1.f / (1.f + __expf(-(xz + s[1])));
            float n_ = tanhf(xn + r_ * s[2]);
            float hnew = (1.f - z_) * n_ + z_ * hreg;
            hreg = hnew;
            g_h[(p ^ 1) * 32 * 1024 + hidx] = hnew;
            __stcs(&out[(size_t)eb * os_b + (size_t)t * os_t + (size_t)jg * os_j], hnew);
            __threadfence();   // make h_new globally visible before barrier release
        }

        // ---- grid-wide barrier (sense via generation counter) ----
        __syncthreads();
        if (tid == 0) {
            unsigned a = atomicAdd(&g_cnt, 1);
            if (a == (unsigned)G - 1) {
                g_cnt = 0;
                __threadfence();
                atomicAdd(&g_gen, 1);
            } else {
                while (*(volatile unsigned*)&g_gen == local_gen) { }
            }
            local_gen++;
        }
        __syncthreads();
    }
}

extern "C" void kernel_launch(void* const* d_in, const int* in_sizes, int n_in,
                              void* d_out, int out_size) {
    const float* x = (const float*)d_in[0];
    const float* wih[4]; const float* whh[4]; const float* bih[4]; const float* bhh[4];
    for (int l = 0; l < 4; ++l) {
        wih[l] = (const float*)d_in[1 + 4 * l];
        whh[l] = (const float*)d_in[2 + 4 * l];
        bih[l] = (const float*)d_in[3 + 4 * l];
        bhh[l] = (const float*)d_in[4 + 4 * l];
    }
    float *xg, *a0, *a1;
    cudaGetSymbolAddress((void**)&xg, g_xg);
    cudaGetSymbolAddress((void**)&a0, g_act0);
    cudaGetSymbolAddress((void**)&a1, g_act1);
    float* dout = (float*)d_out;

    const int SMEM4 = (3 * 4 * 512 + 8 * 12 * 32) * 4;     // 36864 B
    const int SMEM8 = (3 * 8 * 1024 + 8 * 24 * 32) * 4;    // 122880 B
    cudaFuncSetAttribute(recur_kernel<512, 4>, cudaFuncAttributeMaxDynamicSharedMemorySize, SMEM4);
    cudaFuncSetAttribute(recur_kernel<1024, 8>, cudaFuncAttributeMaxDynamicSharedMemorySize, SMEM8);

    struct Cfg { const float* A; int K; int H; long sb, st, sk; float* out; long ob, ot, oj; };
    Cfg cfg[4] = {
        { x,   256,  512, (long)256 * 2048,  1,    2048, a0,   (long)2048 * 512,  512,  1    },
        { a0,  512,  512, (long)2048 * 512,  512,  1,    a1,   (long)2048 * 512,  512,  1    },
        { a1,  512, 1024, (long)2048 * 512,  512,  1,    a0,   (long)2048 * 1024, 1024, 1    },
        { a0, 1024, 1024, (long)2048 * 1024, 1024, 1,    dout, (long)1024 * 2048, 1,    2048 },
    };

    for (int l = 0; l < 4; ++l) {
        int N3 = 3 * cfg[l].H;
        dim3 gg(N3 / 64, (BB * TT) / 128);
        gemm_xg<<<gg, 256>>>(cfg[l].A, wih[l], bih[l], xg,
                             cfg[l].K, N3, cfg[l].sb, cfg[l].st, cfg[l].sk);
        zero_h_kernel<<<64, 1024>>>();
        if (cfg[l].H == 512)
            recur_kernel<512, 4><<<128, 256, SMEM4>>>(xg, whh[l], bhh[l], cfg[l].out,
                                                      cfg[l].ob, cfg[l].ot, cfg[l].oj);
        else
            recur_kernel<1024, 8><<<128, 256, SMEM8>>>(xg, whh[l], bhh[l], cfg[l].out,
                                                       cfg[l].ob, cfg[l].ot, cfg[l].oj);
    }
}

// round 4
// speedup vs baseline: 1.5879x; 1.5879x over previous
#include <cuda_runtime.h>
#include <cstdint>

// Problem constants
constexpr int BB = 32;       // batch
constexpr int TT = 2048;     // time steps

// ---------------- scratch (static device globals; no allocation allowed) ----
__device__ float g_xg[(size_t)BB * TT * 3072];     // input-gate projections, max 3H=3072
__device__ float g_act0[(size_t)BB * TT * 1024];   // activation ping
__device__ float g_act1[(size_t)BB * TT * 1024];   // activation pong
__device__ float g_h[2 * 32 * 1024];               // hidden state, double buffered, layout f4[k>>2][b][k&3]
__device__ unsigned g_cnt;                          // grid barrier counter
__device__ unsigned g_gen;                          // grid barrier generation

// ---------------- packed f32x2 helpers (sm_100+) ---------------------------
__device__ __forceinline__ void fma2(unsigned long long& a, unsigned long long x, unsigned long long y) {
    asm("fma.rn.f32x2 %0, %1, %2, %0;" : "+l"(a) : "l"(x), "l"(y));
}
__device__ __forceinline__ unsigned long long pk2(float x, float y) {
    unsigned long long r; asm("mov.b64 %0, {%1,%2};" : "=l"(r) : "f"(x), "f"(y)); return r;
}
__device__ __forceinline__ float2 up2(unsigned long long v) {
    float2 f; asm("mov.b64 {%0,%1}, %2;" : "=f"(f.x), "=f"(f.y) : "l"(v)); return f;
}

union HU { float4 f; ulonglong2 u; };

__device__ __forceinline__ void cpa16(void* dst, const void* src) {
    uint32_t d = (uint32_t)__cvta_generic_to_shared(dst);
    asm volatile("cp.async.cg.shared.global [%0], [%1], 16;" :: "r"(d), "l"(src));
}

// ---------------- input projection GEMM (round-2 version: known good) -------
// C[m, n] = sum_k A[m, k] * W[n, k] + bias[n],  m = b*TT + t
// Tile: BM=128, BN=64, BK=16; 256 threads; per-thread 8x4 via f32x2 row pairs.
__global__ __launch_bounds__(256) void gemm_xg(
    const float* __restrict__ A, const float* __restrict__ W,
    const float* __restrict__ bias, float* __restrict__ C,
    int K, int N3, long sb, long st, long sk)
{
    __shared__ __align__(16) float As[16][128];
    __shared__ __align__(16) float Bs[16][64];

    int tid = threadIdx.x;
    int n0 = blockIdx.x * 64;
    int m0 = blockIdx.y * 128;
    int bidx = m0 / TT;
    int t0 = m0 % TT;          // TT % 128 == 0 so tile stays within one batch row
    const float* Ab = A + (size_t)bidx * sb + (size_t)t0 * st;
    int tx = tid & 15, ty = tid >> 4;

    unsigned long long acc2[4][4];
#pragma unroll
    for (int i = 0; i < 4; ++i)
#pragma unroll
        for (int j = 0; j < 4; ++j) acc2[i][j] = 0ull;

    for (int k0 = 0; k0 < K; k0 += 16) {
        if (sk == 1) {
#pragma unroll
            for (int i = 0; i < 2; ++i) {
                int lin = tid + i * 256;
                int m = lin >> 2, k4 = (lin & 3) * 4;
                const float* p = Ab + (size_t)m * st + (k0 + k4);
                float4 v = *(const float4*)p;
                As[k4 + 0][m] = v.x; As[k4 + 1][m] = v.y;
                As[k4 + 2][m] = v.z; As[k4 + 3][m] = v.w;
            }
        } else {
#pragma unroll
            for (int i = 0; i < 2; ++i) {
                int lin = tid + i * 256;
                int k = lin >> 5, m4 = (lin & 31) * 4;
                const float* p = Ab + m4 + (size_t)(k0 + k) * sk;
                *(float4*)&As[k][m4] = *(const float4*)p;
            }
        }
        {
            int n = tid >> 2, k4 = (tid & 3) * 4;
            float4 v = *(const float4*)&W[(size_t)(n0 + n) * K + k0 + k4];
            Bs[k4 + 0][n] = v.x; Bs[k4 + 1][n] = v.y;
            Bs[k4 + 2][n] = v.z; Bs[k4 + 3][n] = v.w;
        }
        __syncthreads();

#pragma unroll
        for (int k = 0; k < 16; ++k) {
            const ulonglong2* ap = (const ulonglong2*)&As[k][ty * 8];
            ulonglong2 A0 = ap[0], A1 = ap[1];
            unsigned long long am[4] = {A0.x, A0.y, A1.x, A1.y};
            float4 bv = *(const float4*)&Bs[k][tx * 4];
            unsigned long long bd[4] = {pk2(bv.x, bv.x), pk2(bv.y, bv.y),
                                        pk2(bv.z, bv.z), pk2(bv.w, bv.w)};
#pragma unroll
            for (int mp = 0; mp < 4; ++mp)
#pragma unroll
                for (int j = 0; j < 4; ++j) fma2(acc2[mp][j], am[mp], bd[j]);
        }
        __syncthreads();
    }

    float4 bv = *(const float4*)&bias[n0 + tx * 4];
#pragma unroll
    for (int mp = 0; mp < 4; ++mp) {
        float2 c0 = up2(acc2[mp][0]), c1 = up2(acc2[mp][1]);
        float2 c2 = up2(acc2[mp][2]), c3 = up2(acc2[mp][3]);
        size_t r0 = (size_t)(m0 + ty * 8 + 2 * mp) * N3 + n0 + tx * 4;
        float4 o0 = {c0.x + bv.x, c1.x + bv.y, c2.x + bv.z, c3.x + bv.w};
        float4 o1 = {c0.y + bv.x, c1.y + bv.y, c2.y + bv.z, c3.y + bv.w};
        *(float4*)&C[r0] = o0;
        *(float4*)&C[r0 + N3] = o1;
    }
}

// ---------------- zero hidden state ----------------------------------------
__global__ void zero_h_kernel() {
    int i = blockIdx.x * blockDim.x + threadIdx.x;
    if (i < 2 * 32 * 1024) g_h[i] = 0.f;
}

// ---------------- persistent GRU recurrence --------------------------------
// CTA owns HC hidden indices (3*HC rows of w_hh in SMEM). Each step each warp
// stages ITS OWN k-slice of h via cp.async into per-warp double-buffered SMEM
// chunks (no block sync needed in the pipeline: every lane reads exactly the
// float4s it copied; wait_group is per-thread). FMAs overlap the next chunk's
// loads. Then cross-warp reduction via SMEM, gate math (h_prev in register,
// xg prefetched at step start), h_new store, grid barrier.
template<int K, int HC>
__global__ __launch_bounds__(256) void recur_kernel(
    const float* __restrict__ xg, const float* __restrict__ w_hh,
    const float* __restrict__ b_hh, float* __restrict__ out,
    long os_b, long os_t, long os_j)
{
    constexpr int NR = 3 * HC;
    constexpr int H = K;
    constexpr int k4n = (K / 4) / 8;          // float4 k-groups per warp
    constexpr int CW = 8;                     // k-groups per chunk
    constexpr int NC = k4n / CW;              // chunks per warp (4 for K=1024, 2 for K=512)
    extern __shared__ __align__(16) float smem[];
    float* w_s = smem;                                   // [NR][K]
    float4* hb4 = (float4*)(smem + NR * K);              // [8 warps][2 bufs][CW*32] float4
    float* red = smem + NR * K + 8 * 2 * CW * 32 * 4;    // [8][NR][32]

    int tid = threadIdx.x;
    int cta = blockIdx.x;
    int G = gridDim.x;
    int j0 = cta * HC;

    // load this CTA's w_hh rows into SMEM (rows: gate*H + j0 + jl); zero pad tail
    for (int r = 0; r < NR; ++r) {
        int gate = r / HC, jl = r % HC;
        int j = j0 + jl;
        for (int k = tid * 4; k < K; k += 1024) {
            float4 v = make_float4(0.f, 0.f, 0.f, 0.f);
            if (j < H) v = *(const float4*)&w_hh[(size_t)(gate * H + j) * K + k];
            *(float4*)&w_s[r * K + k] = v;
        }
    }
    unsigned local_gen = 0;
    if (tid == 0) local_gen = *(volatile unsigned*)&g_gen;
    __syncthreads();

    int warp = tid >> 5, lane = tid & 31;
    int k4b = warp * k4n;
    float4* mybuf = hb4 + warp * 2 * CW * 32;            // this warp's two buffers
    const float* wcol0 = w_s + k4b * 4;                  // column base for this warp

    int ejl = tid >> 5, eb = tid & 31;
    int jg = j0 + ejl;
    bool epi = (tid < HC * 32) && (jg < H);
    int hidx = (jg >> 2) * 128 + eb * 4 + (jg & 3);
    const float* xgbase = xg + (size_t)eb * TT * (3 * H) + jg;
    float bh0 = 0.f, bh1 = 0.f, bh2 = 0.f;
    if (epi) { bh0 = b_hh[jg]; bh1 = b_hh[H + jg]; bh2 = b_hh[2 * H + jg]; }
    float hreg = 0.f;

    for (int t = 0; t < TT; ++t) {
        int p = t & 1;
        const float4* hp = (const float4*)&g_h[p * 32 * 1024] + (size_t)k4b * 32;

        // stage first two chunks of this warp's slice
#pragma unroll
        for (int c0 = 0; c0 < 2 && c0 < NC; ++c0) {
            float4* dst = mybuf + c0 * CW * 32;
            const float4* src = hp + c0 * CW * 32;
#pragma unroll
            for (int kk = 0; kk < CW; ++kk)
                cpa16(dst + kk * 32 + lane, src + kk * 32 + lane);
            asm volatile("cp.async.commit_group;" ::: "memory");
        }

        // prefetch xg for this step (result consumed only in epilogue)
        float xr = 0.f, xz = 0.f, xn = 0.f;
        if (epi) {
            const float* xp = xgbase + (size_t)t * (3 * H);
            xr = __ldcs(xp); xz = __ldcs(xp + H); xn = __ldcs(xp + 2 * H);
        }

        unsigned long long acc[NR];
#pragma unroll
        for (int r = 0; r < NR; ++r) acc[r] = 0ull;

#pragma unroll
        for (int c = 0; c < NC; ++c) {
            if (c + 1 < NC) asm volatile("cp.async.wait_group 1;" ::: "memory");
            else            asm volatile("cp.async.wait_group 0;" ::: "memory");
            const float4* buf = mybuf + (c & 1) * CW * 32;
            const float* wc = wcol0 + c * CW * 4;
#pragma unroll
            for (int kk = 0; kk < CW; ++kk) {
                HU hv; hv.f = buf[kk * 32 + lane];
#pragma unroll
                for (int r = 0; r < NR; ++r) {
                    ulonglong2 wv = *(const ulonglong2*)&wc[r * K + kk * 4];
                    fma2(acc[r], hv.u.x, wv.x);
                    fma2(acc[r], hv.u.y, wv.y);
                }
            }
            if (c + 2 < NC) {
                float4* dst = mybuf + (c & 1) * CW * 32;
                const float4* src = hp + (c + 2) * CW * 32;
#pragma unroll
                for (int kk = 0; kk < CW; ++kk)
                    cpa16(dst + kk * 32 + lane, src + kk * 32 + lane);
                asm volatile("cp.async.commit_group;" ::: "memory");
            }
        }

        // cross-warp reduction via SMEM
#pragma unroll
        for (int r = 0; r < NR; ++r) {
            float2 f = up2(acc[r]);
            red[(warp * NR + r) * 32 + lane] = f.x + f.y;
        }
        __syncthreads();

        if (epi) {
            float s[3];
#pragma unroll
            for (int gate = 0; gate < 3; ++gate) {
                float v = (gate == 0) ? bh0 : (gate == 1) ? bh1 : bh2;
#pragma unroll
                for (int w = 0; w < 8; ++w)
                    v += red[(w * NR + gate * HC + ejl) * 32 + eb];
                s[gate] = v;
            }
            float r_ = 1.f / (1.f + __expf(-(xr + s[0])));
            float z_ = 1.f / (1.f + __expf(-(xz + s[1])));
            float n_ = tanhf(xn + r_ * s[2]);
            float hnew = (1.f - z_) * n_ + z_ * hreg;
            hreg = hnew;
            g_h[(p ^ 1) * 32 * 1024 + hidx] = hnew;
            __stcs(&out[(size_t)eb * os_b + (size_t)t * os_t + (size_t)jg * os_j], hnew);
            __threadfence();   // release h_new before this CTA's barrier arrival
        }

        // ---- grid-wide barrier (sense via generation counter) ----
        __syncthreads();
        if (tid == 0) {
            unsigned a = atomicAdd(&g_cnt, 1);
            if (a == (unsigned)G - 1) {
                g_cnt = 0;
                __threadfence();
                atomicAdd(&g_gen, 1);
            } else {
                while (*(volatile unsigned*)&g_gen == local_gen) { }
            }
            local_gen++;
        }
        __syncthreads();
    }
}

extern "C" void kernel_launch(void* const* d_in, const int* in_sizes, int n_in,
                              void* d_out, int out_size) {
    const float* x = (const float*)d_in[0];
    const float* wih[4]; const float* whh[4]; const float* bih[4]; const float* bhh[4];
    for (int l = 0; l < 4; ++l) {
        wih[l] = (const float*)d_in[1 + 4 * l];
        whh[l] = (const float*)d_in[2 + 4 * l];
        bih[l] = (const float*)d_in[3 + 4 * l];
        bhh[l] = (const float*)d_in[4 + 4 * l];
    }
    float *xg, *a0, *a1;
    cudaGetSymbolAddress((void**)&xg, g_xg);
    cudaGetSymbolAddress((void**)&a0, g_act0);
    cudaGetSymbolAddress((void**)&a1, g_act1);
    float* dout = (float*)d_out;

    // SMEM: w_s + h chunk buffers (8 warps * 2 bufs * 8 groups * 32 f4 = 64KB) + red
    const int SMEM4 = (3 * 4 * 512) * 4 + 65536 + (8 * 12 * 32) * 4;    // 102400 B
    const int SMEM7 = (3 * 7 * 1024) * 4 + 65536 + (8 * 21 * 32) * 4;   // 173056 B
    cudaFuncSetAttribute(recur_kernel<512, 4>, cudaFuncAttributeMaxDynamicSharedMemorySize, SMEM4);
    cudaFuncSetAttribute(recur_kernel<1024, 7>, cudaFuncAttributeMaxDynamicSharedMemorySize, SMEM7);

    struct Cfg { const float* A; int K; int H; long sb, st, sk; float* out; long ob, ot, oj; };
    Cfg cfg[4] = {
        { x,   256,  512, (long)256 * 2048,  1,    2048, a0,   (long)2048 * 512,  512,  1    },
        { a0,  512,  512, (long)2048 * 512,  512,  1,    a1,   (long)2048 * 512,  512,  1    },
        { a1,  512, 1024, (long)2048 * 512,  512,  1,    a0,   (long)2048 * 1024, 1024, 1    },
        { a0, 1024, 1024, (long)2048 * 1024, 1024, 1,    dout, (long)1024 * 2048, 1,    2048 },
    };

    for (int l = 0; l < 4; ++l) {
        int N3 = 3 * cfg[l].H;
        dim3 gg(N3 / 64, (BB * TT) / 128);
        gemm_xg<<<gg, 256>>>(cfg[l].A, wih[l], bih[l], xg,
                             cfg[l].K, N3, cfg[l].sb, cfg[l].st, cfg[l].sk);
        zero_h_kernel<<<64, 1024>>>();
        if (cfg[l].H == 512)
            recur_kernel<512, 4><<<128, 256, SMEM4>>>(xg, whh[l], bhh[l], cfg[l].out,
                                                      cfg[l].ob, cfg[l].ot, cfg[l].oj);
        else
            recur_kernel<1024, 7><<<147, 256, SMEM7>>>(xg, whh[l], bhh[l], cfg[l].out,
                                                       cfg[l].ob, cfg[l].ot, cfg[l].oj);
    }
}